// round 8
// baseline (speedup 1.0000x reference)
#include <cuda_runtime.h>
#include <cuda_bf16.h>
#include <math.h>

#define Gn 8
#define Mn 1024
#define Hn 256
#define HEADSn 8
#define HDn 32
#define FFNn 1024
#define Nn (Gn*Mn)          // 8192
#define En 131072
#define MWn (Mn/32)         // 32

typedef __nv_bfloat16 bf16;

// ---------------- scratch (device globals: no allocation allowed) ----------
static __device__ float g_xw[Nn*Hn];
static __device__ float g_xlocal[Nn*Hn];
static __device__ float g_dinv[Nn];
static __device__ int   g_deg[Nn];
static __device__ unsigned g_adj[Gn*Mn*MWn];
static __device__ unsigned char g_dist[(size_t)Gn*Mn*Mn];   // 8 MB
static __device__ float g_buf[Nn*Hn];
static __device__ float g_h[Nn*Hn];
static __device__ float g_h2[Nn*Hn];
static __device__ float g_y[Nn*Hn];
static __device__ int   g_off[Nn+1];
static __device__ int   g_cursor[Nn];
static __device__ int   g_eord[En];     // src node per CSR slot (sorted by dst)
// bf16 operand buffers
static __device__ bf16  g_x_bf[Nn*Hn];
static __device__ bf16  g_qkv_bf[Nn*3*Hn];
static __device__ bf16  g_attn_bf[Nn*Hn];
static __device__ bf16  g_h_bf[Nn*Hn];
static __device__ bf16  g_y_bf[Nn*Hn];
static __device__ bf16  g_ff_bf[Nn*FFNn];
// bf16 weights
static __device__ bf16  g_wgcn[Hn*Hn];
static __device__ bf16  g_wqkv[3*Hn*Hn];
static __device__ bf16  g_wproj[Hn*Hn];
static __device__ bf16  g_wf1[FFNn*Hn];
static __device__ bf16  g_wf2[Hn*FFNn];
static __device__ bf16  g_wo1[FFNn*Hn];
static __device__ bf16  g_wo2[Hn*FFNn];

// ---------------- helpers ---------------------------------------------------
__device__ __forceinline__ float gelu_exact(float x) {
    return 0.5f * x * (1.0f + erff(x * 0.7071067811865475f));
}

__device__ __forceinline__ unsigned packbf(float lo, float hi) {
    unsigned r;
    asm("cvt.rn.bf16x2.f32 %0, %1, %2;" : "=r"(r) : "f"(hi), "f"(lo));
    return r;
}

__device__ __forceinline__ void mma_bf16(float c[4], const unsigned a[4],
                                         unsigned b0, unsigned b1) {
    asm volatile(
        "mma.sync.aligned.m16n8k16.row.col.f32.bf16.bf16.f32 "
        "{%0,%1,%2,%3},{%4,%5,%6,%7},{%8,%9},{%0,%1,%2,%3};"
        : "+f"(c[0]), "+f"(c[1]), "+f"(c[2]), "+f"(c[3])
        : "r"(a[0]), "r"(a[1]), "r"(a[2]), "r"(a[3]), "r"(b0), "r"(b1));
}

__device__ __forceinline__ void cp8(unsigned dst, const void* src) {
    asm volatile("cp.async.ca.shared.global [%0], [%1], 8;"
        :: "r"(dst), "l"(__cvta_generic_to_global(src)));
}
__device__ __forceinline__ void cp_commit() {
    asm volatile("cp.async.commit_group;" ::: "memory");
}
__device__ __forceinline__ void cp_wait1() {
    asm volatile("cp.async.wait_group 1;" ::: "memory");
}

// ---------------- init: deg=1, adj=0, convert weights+x to bf16 -------------
__device__ __forceinline__ void cvt4seg(const float* __restrict__ s,
                                        bf16* __restrict__ d, int q) {
    float4 v = *(const float4*)(s + (size_t)q*4);
    *(uint2*)(d + (size_t)q*4) = make_uint2(packbf(v.x, v.y), packbf(v.z, v.w));
}

__global__ void init_cvt_kernel(
    const float* __restrict__ x, const float* __restrict__ gcn_w,
    const float* __restrict__ qkv_w, const float* __restrict__ proj_w,
    const float* __restrict__ ffn1_w, const float* __restrict__ ffn2_w,
    const float* __restrict__ offn1_w, const float* __restrict__ offn2_w)
{
    int i = blockIdx.x * blockDim.x + threadIdx.x;
    if (i < Nn) g_deg[i] = 1;
    if (i < Gn*Mn*MWn) g_adj[i] = 0;
    int q = i;
    if (q < 524288) { cvt4seg(x, g_x_bf, q); return; }        q -= 524288;
    if (q < 16384)  { cvt4seg(gcn_w, g_wgcn, q); return; }    q -= 16384;
    if (q < 49152)  { cvt4seg(qkv_w, g_wqkv, q); return; }    q -= 49152;
    if (q < 16384)  { cvt4seg(proj_w, g_wproj, q); return; }  q -= 16384;
    if (q < 65536)  { cvt4seg(ffn1_w, g_wf1, q); return; }    q -= 65536;
    if (q < 65536)  { cvt4seg(ffn2_w, g_wf2, q); return; }    q -= 65536;
    if (q < 65536)  { cvt4seg(offn1_w, g_wo1, q); return; }   q -= 65536;
    if (q < 65536)  { cvt4seg(offn2_w, g_wo2, q); return; }
}

__global__ void edge_prep_kernel(const int* __restrict__ src, const int* __restrict__ dst) {
    int e = blockIdx.x * blockDim.x + threadIdx.x;
    if (e >= En) return;
    int s = src[e], d = dst[e];
    atomicAdd(&g_deg[d], 1);
    if (s != d) {
        int g  = s >> 10;
        int ls = s & 1023, ld = d & 1023;
        atomicOr(&g_adj[(g*Mn + ls)*MWn + (ld >> 5)], 1u << (ld & 31));
        atomicOr(&g_adj[(g*Mn + ld)*MWn + (ls >> 5)], 1u << (ls & 31));
    }
}

// ---------------- scan: offsets + cursor + dinv (1 block, 1024 thr) --------
__global__ __launch_bounds__(1024) void scan_kernel() {
    __shared__ int wsum[32];
    int t = threadIdx.x, lane = t & 31, w = t >> 5;
    int base = t * 8;
    int loc[8]; int s = 0;
#pragma unroll
    for (int j = 0; j < 8; j++) {
        int dg = g_deg[base + j];
        g_dinv[base + j] = rsqrtf((float)dg);
        loc[j] = dg - 1; s += loc[j];
    }
    int inc = s;
#pragma unroll
    for (int d = 1; d < 32; d <<= 1) {
        int v = __shfl_up_sync(0xffffffffu, inc, d);
        if (lane >= d) inc += v;
    }
    if (lane == 31) wsum[w] = inc;
    __syncthreads();
    if (w == 0) {
        int v = wsum[lane];
#pragma unroll
        for (int d = 1; d < 32; d <<= 1) {
            int u = __shfl_up_sync(0xffffffffu, v, d);
            if (lane >= d) v += u;
        }
        wsum[lane] = v;
    }
    __syncthreads();
    int excl = inc - s + (w ? wsum[w-1] : 0);
#pragma unroll
    for (int j = 0; j < 8; j++) {
        g_off[base + j] = excl;
        g_cursor[base + j] = excl;
        excl += loc[j];
    }
    if (t == 1023) g_off[Nn] = excl;
}

// ---------------- body: CSR fill --------------------------------------------
__device__ __forceinline__ void fill_body(int e, const int* __restrict__ src,
                                          const int* __restrict__ dst) {
    if (e >= En) return;
    int d = dst[e];
    int pos = atomicAdd(&g_cursor[d], 1);
    g_eord[pos] = src[e];
}

// ---------------- body: GCN gather (1 block per dst node) -------------------
__device__ __forceinline__ void gather_body(int d, int t, const float* __restrict__ gcn_b) {
    float dinvd = g_dinv[d];
    float acc = g_xw[(size_t)d*Hn + t] * dinvd * dinvd + gcn_b[t];
    int beg = g_off[d], end = g_off[d+1];
    int e = beg;
    for (; e + 2 <= end; e += 2) {
        int s0 = g_eord[e], s1 = g_eord[e+1];
        float w0 = g_dinv[s0] * dinvd;
        float w1 = g_dinv[s1] * dinvd;
        float v0 = g_xw[(size_t)s0*Hn + t];
        float v1 = g_xw[(size_t)s1*Hn + t];
        acc += v0 * w0 + v1 * w1;
    }
    if (e < end) {
        int s0 = g_eord[e];
        acc += g_xw[(size_t)s0*Hn + t] * (g_dinv[s0] * dinvd);
    }
    g_xlocal[(size_t)d*Hn + t] = acc;
}

// ---------------- body: SPD bitset BFS, direction-optimal, batch-4 ---------
__device__ __forceinline__ int warp_sum(int v) {
#pragma unroll
    for (int d = 16; d; d >>= 1) v += __shfl_xor_sync(0xffffffffu, v, d);
    return v;
}

__device__ __forceinline__ void bfs_body(int row, int lane) {
    int g = row >> 10, i = row & 1023;
    const unsigned* gadj = g_adj + (size_t)g * Mn * MWn;
    unsigned frontier = gadj[(size_t)i * MWn + lane];
    unsigned diag = ((i >> 5) == lane) ? (1u << (i & 31)) : 0u;
    unsigned visited = frontier | diag;
    unsigned char* drow = g_dist + (size_t)row * Mn;

    // dist row init: 1 where adj, 0 on diag, 6 elsewhere; packed 4B stores
#pragma unroll
    for (int p = 0; p < 8; p++) {
        unsigned word = 0;
#pragma unroll
        for (int b = 0; b < 4; b++) {
            int bi = p*4 + b;
            int k = lane*32 + bi;
            unsigned char v = ((frontier >> bi) & 1u) ? 1 : ((k == i) ? 0 : 6);
            word |= ((unsigned)v) << (8*b);
        }
        *(unsigned*)(drow + lane*32 + p*4) = word;
    }

    for (int d = 2; d <= 5; d++) {
        int cf = warp_sum(__popc(frontier));
        if (cf == 0) break;
        int cu = 1024 - warp_sum(__popc(visited));
        if (cu == 0) break;
        unsigned newf = 0;
        if (cf <= cu) {
            // forward: expand frontier rows, batch-4 loads (MLP=4)
            int j0 = 0, j1 = 0, j2 = 0, j3 = 0, cnt = 0;
#pragma unroll 1
            for (int ws = 0; ws < 32; ws++) {
                unsigned fw = __shfl_sync(0xffffffffu, frontier, ws);
                int base = ws * 32;
                while (fw) {
                    int b = __ffs(fw) - 1; fw &= fw - 1;
                    int j = base + b;
                    if (cnt == 0) j0 = j; else if (cnt == 1) j1 = j;
                    else if (cnt == 2) j2 = j; else j3 = j;
                    if (++cnt == 4) {
                        unsigned v0 = gadj[(size_t)j0*MWn + lane];
                        unsigned v1 = gadj[(size_t)j1*MWn + lane];
                        unsigned v2 = gadj[(size_t)j2*MWn + lane];
                        unsigned v3 = gadj[(size_t)j3*MWn + lane];
                        newf |= (v0 | v1) | (v2 | v3);
                        cnt = 0;
                    }
                }
            }
            if (cnt > 0) {
                newf |= gadj[(size_t)j0*MWn + lane];
                if (cnt > 1) newf |= gadj[(size_t)j1*MWn + lane];
                if (cnt > 2) newf |= gadj[(size_t)j2*MWn + lane];
            }
            newf &= ~visited;
        } else {
            // reverse: probe unvisited rows against frontier, batch-4
            unsigned unv = ~visited;
            int j0 = 0, j1 = 0, j2 = 0, j3 = 0, cnt = 0;
#pragma unroll 1
            for (int ws = 0; ws < 32; ws++) {
                unsigned uw = __shfl_sync(0xffffffffu, unv, ws);
                int base = ws * 32;
                while (uw) {
                    int b = __ffs(uw) - 1; uw &= uw - 1;
                    int j = base + b;
                    if (cnt == 0) j0 = j; else if (cnt == 1) j1 = j;
                    else if (cnt == 2) j2 = j; else j3 = j;
                    if (++cnt == 4) {
                        unsigned v0 = gadj[(size_t)j0*MWn + lane];
                        unsigned v1 = gadj[(size_t)j1*MWn + lane];
                        unsigned v2 = gadj[(size_t)j2*MWn + lane];
                        unsigned v3 = gadj[(size_t)j3*MWn + lane];
                        unsigned m0 = __ballot_sync(0xffffffffu, (v0 & frontier) != 0u);
                        unsigned m1 = __ballot_sync(0xffffffffu, (v1 & frontier) != 0u);
                        unsigned m2 = __ballot_sync(0xffffffffu, (v2 & frontier) != 0u);
                        unsigned m3 = __ballot_sync(0xffffffffu, (v3 & frontier) != 0u);
                        if (m0 && lane == (j0 >> 5)) newf |= 1u << (j0 & 31);
                        if (m1 && lane == (j1 >> 5)) newf |= 1u << (j1 & 31);
                        if (m2 && lane == (j2 >> 5)) newf |= 1u << (j2 & 31);
                        if (m3 && lane == (j3 >> 5)) newf |= 1u << (j3 & 31);
                        cnt = 0;
                    }
                }
            }
            if (cnt > 0) {   // cnt is warp-uniform: ballots are safe
                unsigned v0 = gadj[(size_t)j0*MWn + lane];
                unsigned m0 = __ballot_sync(0xffffffffu, (v0 & frontier) != 0u);
                if (m0 && lane == (j0 >> 5)) newf |= 1u << (j0 & 31);
                if (cnt > 1) {
                    unsigned v1 = gadj[(size_t)j1*MWn + lane];
                    unsigned m1 = __ballot_sync(0xffffffffu, (v1 & frontier) != 0u);
                    if (m1 && lane == (j1 >> 5)) newf |= 1u << (j1 & 31);
                }
                if (cnt > 2) {
                    unsigned v2 = gadj[(size_t)j2*MWn + lane];
                    unsigned m2 = __ballot_sync(0xffffffffu, (v2 & frontier) != 0u);
                    if (m2 && lane == (j2 >> 5)) newf |= 1u << (j2 & 31);
                }
            }
        }
        visited |= newf;
        unsigned t = newf;
        while (t) {
            int b = __ffs(t) - 1; t &= t - 1;
            drow[lane*32 + b] = (unsigned char)d;
        }
        frontier = newf;
    }
}

// ---------------- body: bf16 tensor-core GEMM, cp.async 3-stage -------------
// C[M,Nc] = act(A[M,K] * B[Nc,K]^T + bias). A,B bf16 in gmem; C fp32 or bf16.
template<int BM>
__device__ __forceinline__ void gemm_body(
    const bf16* __restrict__ A, const bf16* __restrict__ B,
    const float* __restrict__ bias, void* __restrict__ Cv,
    int Nc, int K, int act, int obf, int bx, int by, unsigned* sm)
{
    constexpr int WMW = (BM == 128) ? 4 : 2;
    constexpr int WNW = 8 / WMW;
    constexpr int WTN = 64 / WNW;
    constexpr int NT  = WTN / 8;
    constexpr int A4  = BM / 32;
    constexpr int STG = (BM + 64) * 20;

    int bm = by * BM, bn = bx * 64;
    int tid = threadIdx.x;
    int warp = tid >> 5, lane = tid & 31;
    int wm = warp / WNW, wn = warp % WNW;
    int lr = lane >> 2, lc = lane & 3;

    // per-thread load coordinates (A4 segments for A, 2 for B)
    int rA[A4], cA;   // row + col4 (same col4 pattern for all segs of a thread)
    {
        cA = (tid & 7) * 4;
#pragma unroll
        for (int l = 0; l < A4; l++) rA[l] = (tid + l*256) >> 3;
    }
    int pcol = (tid & 7) * 2;

    auto issue = [&](int it) {
        int k0 = it << 5;
        unsigned* buf = sm + (it % 3) * STG;
        unsigned* AH = buf;
        unsigned* BH = buf + BM*20;
#pragma unroll
        for (int l = 0; l < A4; l++)
            cp8((unsigned)__cvta_generic_to_shared(&AH[rA[l]*20 + pcol]),
                A + (size_t)(bm + rA[l]) * K + k0 + cA);
#pragma unroll
        for (int l = 0; l < 2; l++) {
            int row = (tid + l*256) >> 3;
            cp8((unsigned)__cvta_generic_to_shared(&BH[row*20 + pcol]),
                B + (size_t)(bn + row) * K + k0 + cA);
        }
    };

    float acc[2][NT][4];
#pragma unroll
    for (int i = 0; i < 2; i++)
#pragma unroll
        for (int j = 0; j < NT; j++)
#pragma unroll
            for (int r = 0; r < 4; r++) acc[i][j][r] = 0.0f;

    int nk = K >> 5;
    issue(0); cp_commit();
    issue(1); cp_commit();

    for (int it = 0; it < nk; it++) {
        cp_wait1();
        __syncthreads();
        unsigned* AH = sm + (it % 3) * STG;
        unsigned* BH = AH + BM*20;

#pragma unroll
        for (int ks = 0; ks < 2; ks++) {
            int pb = ks * 8;
            unsigned ah[2][4];
#pragma unroll
            for (int mt = 0; mt < 2; mt++) {
                int rr = wm*32 + mt*16;
                ah[mt][0] = AH[(rr+lr  )*20 + pb + lc];
                ah[mt][1] = AH[(rr+lr+8)*20 + pb + lc];
                ah[mt][2] = AH[(rr+lr  )*20 + pb + 4 + lc];
                ah[mt][3] = AH[(rr+lr+8)*20 + pb + 4 + lc];
            }
#pragma unroll
            for (int nt = 0; nt < NT; nt++) {
                int cB = wn*WTN + nt*8;
                unsigned bh0 = BH[(cB+lr)*20 + pb + lc];
                unsigned bh1 = BH[(cB+lr)*20 + pb + 4 + lc];
#pragma unroll
                for (int mt = 0; mt < 2; mt++)
                    mma_bf16(acc[mt][nt], ah[mt], bh0, bh1);
            }
        }

        if (it + 2 < nk) issue(it + 2);
        cp_commit();
    }

    // ---- epilogue ----
#pragma unroll
    for (int mt = 0; mt < 2; mt++) {
#pragma unroll
        for (int nt = 0; nt < NT; nt++) {
            int m = bm + wm*32 + mt*16 + lr;
            int n = bn + wn*WTN + nt*8 + lc*2;
            float b0 = 0.0f, b1 = 0.0f;
            if (bias) { b0 = bias[n]; b1 = bias[n+1]; }
            float v0 = acc[mt][nt][0] + b0;
            float v1 = acc[mt][nt][1] + b1;
            float v2 = acc[mt][nt][2] + b0;
            float v3 = acc[mt][nt][3] + b1;
            if (act) { v0 = gelu_exact(v0); v1 = gelu_exact(v1);
                       v2 = gelu_exact(v2); v3 = gelu_exact(v3); }
            if (obf) {
                bf16* C = (bf16*)Cv;
                *(unsigned*)(C + (size_t)m * Nc + n)     = packbf(v0, v1);
                *(unsigned*)(C + (size_t)(m+8) * Nc + n) = packbf(v2, v3);
            } else {
                float* C = (float*)Cv;
                *(float2*)(C + (size_t)m * Nc + n)     = make_float2(v0, v1);
                *(float2*)(C + (size_t)(m+8) * Nc + n) = make_float2(v2, v3);
            }
        }
    }
}

template<int BM>
__global__ __launch_bounds__(256) void gemm_bf16_kernel(
    const bf16* __restrict__ A, const bf16* __restrict__ B,
    const float* __restrict__ bias, void* __restrict__ C,
    int Nc, int K, int act, int obf)
{
    extern __shared__ unsigned sm[];
    gemm_body<BM>(A, B, bias, C, Nc, K, act, obf, blockIdx.x, blockIdx.y, sm);
}

// ---------------- attention: all-bf16 src, register softmax, double-buffer -
// smem layout (u32 offsets):
//   Ks[2]  : 0    + s*1280  (64 rows x 20 u32)
//   VsT[2] : 2560 + s*1152  (32 rows x 36 u32)
//   ds[2]  : 4864 + s*2176  (128 rows x 17 u32)
//   btab   : 9216 (8 floats)
#define ATTN_SMEM_U32 9224

__device__ __forceinline__ void attn_body(const float* __restrict__ bias_emb,
                                          int g, int head, int q0, unsigned* sm) {
    int tid = threadIdx.x;
    int warp = tid >> 5, lane = tid & 31;
    int lr = lane >> 2, lc = lane & 3;
    int qb = warp * 16;
    const float scale = 0.17677669529663687f;   // 32^-0.5

    float* btab = (float*)(sm + 9216);
    if (tid < 7) btab[tid] = bias_emb[tid];

    // Q fragments in registers (bf16; scale folded into post-MMA FMA)
    unsigned aq[2][4];
    {
        size_t r0 = (size_t)(g*Mn + q0 + qb + lr)*768 + head*32;
        size_t r1 = (size_t)(g*Mn + q0 + qb + lr + 8)*768 + head*32;
#pragma unroll
        for (int ch = 0; ch < 2; ch++) {
            aq[ch][0] = *(const unsigned*)(g_qkv_bf + r0 + 16*ch + 2*lc);
            aq[ch][1] = *(const unsigned*)(g_qkv_bf + r1 + 16*ch + 2*lc);
            aq[ch][2] = *(const unsigned*)(g_qkv_bf + r0 + 16*ch + 8 + 2*lc);
            aq[ch][3] = *(const unsigned*)(g_qkv_bf + r1 + 16*ch + 8 + 2*lc);
        }
    }

    float acc[4][4];
#pragma unroll
    for (int i = 0; i < 4; i++)
#pragma unroll
        for (int j = 0; j < 4; j++) acc[i][j] = 0.0f;
    float m0 = -1e30f, m1 = -1e30f, l0 = 0.0f, l1 = 0.0f;

    // ---- coop load tile 0 into stage 0 ----
    {
        unsigned* Ks = sm;
        bf16* Vt16 = (bf16*)(sm + 2560);
        unsigned* ds = sm + 4864;
#pragma unroll
        for (int l = 0; l < 4; l++) {
            int e = tid + l*256;
            int row = e >> 4, j = e & 15;
            size_t base = (size_t)(g*Mn + row)*768 + head*32 + 2*j;
            Ks[row*20 + j] = *(const unsigned*)(g_qkv_bf + base + 256);
            __nv_bfloat162 vv = *(const __nv_bfloat162*)(g_qkv_bf + base + 512);
            Vt16[(2*j)*72 + row]   = vv.x;
            Vt16[(2*j+1)*72 + row] = vv.y;
        }
#pragma unroll
        for (int l = 0; l < 2; l++) {
            int e = tid + l*256;
            int row = e >> 2, qd = e & 3;
            uint4 dv = *(const uint4*)&g_dist[(size_t)(g*Mn + q0 + row)*Mn + qd*16];
            ds[row*17 + qd*4 + 0] = dv.x;
            ds[row*17 + qd*4 + 1] = dv.y;
            ds[row*17 + qd*4 + 2] = dv.z;
            ds[row*17 + qd*4 + 3] = dv.w;
        }
    }
    __syncthreads();

    for (int tk = 0; tk < 16; tk++) {
        int s = tk & 1;
        unsigned* Ks = sm + s*1280;
        unsigned* Vt = sm + 2560 + s*1152;
        const unsigned short* ds16 = (const unsigned short*)(sm + 4864 + s*2176);

        // prefetch next tile
        unsigned pk[4];
        __nv_bfloat162 pv[4];
        uint4 pd[2];
        bool has = (tk + 1 < 16);
        if (has) {
            int krow0 = (tk + 1) * 64;
#pragma unroll
            for (int l = 0; l < 4; l++) {
                int e = tid + l*256;
                int row = e >> 4, j = e & 15;
                size_t base = (size_t)(g*Mn + krow0 + row)*768 + head*32 + 2*j;
                pk[l] = *(const unsigned*)(g_qkv_bf + base + 256);
                pv[l] = *(const __nv_bfloat162*)(g_qkv_bf + base + 512);
            }
#pragma unroll
            for (int l = 0; l < 2; l++) {
                int e = tid + l*256;
                int row = e >> 2, qd = e & 3;
                pd[l] = *(const uint4*)&g_dist[(size_t)(g*Mn + q0 + row)*Mn + krow0 + qd*16];
            }
        }

        // ---- QK^T ----
        float sc[8][4];
#pragma unroll
        for (int nt = 0; nt < 8; nt++)
#pragma unroll
            for (int r = 0; r < 4; r++) sc[nt][r] = 0.0f;
#pragma unroll
        for (int ch = 0; ch < 2; ch++) {
#pragma unroll
            for (int nt = 0; nt < 8; nt++) {
                unsigned b0 = Ks[(nt*8+lr)*20 + 8*ch + lc];
                unsigned b1 = Ks[(nt*8+lr)*20 + 8*ch + 4 + lc];
                mma_bf16(sc[nt], aq[ch], b0, b1);
            }
        }

        // ---- scale + bias + row max (registers) ----
        float mn0 = m0, mn1 = m1;
#pragma unroll
        for (int nt = 0; nt < 8; nt++) {
            unsigned short w0 = ds16[(qb+lr)*34 + nt*4 + lc];
            unsigned short w1 = ds16[(qb+lr+8)*34 + nt*4 + lc];
            sc[nt][0] = fmaf(sc[nt][0], scale, btab[w0 & 255]);
            sc[nt][1] = fmaf(sc[nt][1], scale, btab[w0 >> 8]);
            sc[nt][2] = fmaf(sc[nt][2], scale, btab[w1 & 255]);
            sc[nt][3] = fmaf(sc[nt][3], scale, btab[w1 >> 8]);
            mn0 = fmaxf(mn0, fmaxf(sc[nt][0], sc[nt][1]));
            mn1 = fmaxf(mn1, fmaxf(sc[nt][2], sc[nt][3]));
        }
        mn0 = fmaxf(mn0, __shfl_xor_sync(0xffffffffu, mn0, 1));
        mn0 = fmaxf(mn0, __shfl_xor_sync(0xffffffffu, mn0, 2));
        mn1 = fmaxf(mn1, __shfl_xor_sync(0xffffffffu, mn1, 1));
        mn1 = fmaxf(mn1, __shfl_xor_sync(0xffffffffu, mn1, 2));
        float f0 = __expf(m0 - mn0);
        float f1 = __expf(m1 - mn1);

        // ---- exp + sum + pack P ----
        float rs0 = 0.0f, rs1 = 0.0f;
#pragma unroll
        for (int nt = 0; nt < 8; nt++) {
            float e0 = __expf(sc[nt][0] - mn0);
            float e1 = __expf(sc[nt][1] - mn0);
            float e2 = __expf(sc[nt][2] - mn1);
            float e3 = __expf(sc[nt][3] - mn1);
            rs0 += e0 + e1; rs1 += e2 + e3;
            sc[nt][0] = e0; sc[nt][1] = e1; sc[nt][2] = e2; sc[nt][3] = e3;
        }
        unsigned P[4][4];
#pragma unroll
        for (int ch = 0; ch < 4; ch++) {
            P[ch][0] = packbf(sc[2*ch][0],   sc[2*ch][1]);
            P[ch][1] = packbf(sc[2*ch][2],   sc[2*ch][3]);
            P[ch][2] = packbf(sc[2*ch+1][0], sc[2*ch+1][1]);
            P[ch][3] = packbf(sc[2*ch+1][2], sc[2*ch+1][3]);
        }
        rs0 += __shfl_xor_sync(0xffffffffu, rs0, 1);
        rs0 += __shfl_xor_sync(0xffffffffu, rs0, 2);
        rs1 += __shfl_xor_sync(0xffffffffu, rs1, 1);
        rs1 += __shfl_xor_sync(0xffffffffu, rs1, 2);
        l0 = l0*f0 + rs0; l1 = l1*f1 + rs1;
        m0 = mn0; m1 = mn1;

        // ---- rescale + PV ----
#pragma unroll
        for (int dt = 0; dt < 4; dt++) {
            acc[dt][0] *= f0; acc[dt][1] *= f0;
            acc[dt][2] *= f1; acc[dt][3] *= f1;
        }
#pragma unroll
        for (int ch = 0; ch < 4; ch++) {
#pragma unroll
            for (int dt = 0; dt < 4; dt++) {
                unsigned b0 = Vt[(dt*8+lr)*36 + 8*ch + lc];
                unsigned b1 = Vt[(dt*8+lr)*36 + 8*ch + 4 + lc];
                mma_bf16(acc[dt], P[ch], b0, b1);
            }
        }

        // ---- store prefetched tile into other stage ----
        if (has) {
            unsigned* nKs = sm + (s^1)*1280;
            bf16* nVt16 = (bf16*)(sm + 2560 + (s^1)*1152);
            unsigned* nds = sm + 4864 + (s^1)*2176;
#pragma unroll
            for (int l = 0; l < 4; l++) {
                int e = tid + l*256;
                int row = e >> 4, j = e & 15;
                nKs[row*20 + j] = pk[l];
                nVt16[(2*j)*72 + row]   = pv[l].x;
                nVt16[(2*j+1)*72 + row] = pv[l].y;
            }
#pragma unroll
            for (int l = 0; l < 2; l++) {
                int e = tid + l*256;
                int row = e >> 2, qd = e & 3;
                nds[row*17 + qd*4 + 0] = pd[l].x;
                nds[row*17 + qd*4 + 1] = pd[l].y;
                nds[row*17 + qd*4 + 2] = pd[l].z;
                nds[row*17 + qd*4 + 3] = pd[l].w;
            }
        }
        __syncthreads();
    }

    // ---- epilogue: write bf16 for proj GEMM ----
    float il0 = 1.0f / l0, il1 = 1.0f / l1;
#pragma unroll
    for (int dt = 0; dt < 4; dt++) {
        int d = head*32 + dt*8 + 2*lc;
        *(unsigned*)(g_attn_bf + (size_t)(g*Mn + q0 + qb + lr  )*Hn + d) =
            packbf(acc[dt][0]*il0, acc[dt][1]*il0);
        *(unsigned*)(g_attn_bf + (size_t)(g*Mn + q0 + qb + lr+8)*Hn + d) =
            packbf(acc[dt][2]*il1, acc[dt][3]*il1);
    }
}

// ---------------- fused launches --------------------------------------------
__global__ __launch_bounds__(256) void k_fill_xw(
    const int* __restrict__ src, const int* __restrict__ dst,
    float* __restrict__ xw)
{
    extern __shared__ unsigned sm[];
    int bid = blockIdx.x;
    if (bid < 512) {
        gemm_body<64>(g_x_bf, g_wgcn, nullptr, xw, 256, 256, 0, 0, bid & 3, bid >> 2, sm);
    } else {
        fill_body((bid - 512) * 256 + threadIdx.x, src, dst);
    }
}

__global__ __launch_bounds__(256) void k_qkv_bfs(const float* __restrict__ qkv_b)
{
    extern __shared__ unsigned sm[];
    int bid = blockIdx.x;
    if (bid < 768) {
        gemm_body<128>(g_x_bf, g_wqkv, qkv_b, g_qkv_bf, 768, 256, 0, 1, bid % 12, bid / 12, sm);
    } else {
        int row = (bid - 768) * 8 + (threadIdx.x >> 5);
        bfs_body(row, threadIdx.x & 31);
    }
}

__global__ __launch_bounds__(256) void k_attn_gather(
    const float* __restrict__ bias_emb, const float* __restrict__ gcn_b)
{
    extern __shared__ unsigned sm[];
    int bid = blockIdx.x;
    if (bid < 512) {
        attn_body(bias_emb, bid >> 6, (bid >> 3) & 7, (bid & 7) * 128, sm);
    } else {
        gather_body(bid - 512, threadIdx.x, gcn_b);
    }
}

// ---------------- LayerNorm: out = LN(a [+ b] [+ c]) * gamma + beta --------
__global__ __launch_bounds__(256) void ln_kernel(
    const float* __restrict__ a, const float* __restrict__ b, const float* __restrict__ c,
    const float* __restrict__ gam, const float* __restrict__ bet,
    float* __restrict__ out, bf16* __restrict__ outb)
{
    __shared__ float s1[8], s2[8];
    int row = blockIdx.x, t = threadIdx.x;
    int w = t >> 5;
    size_t off = (size_t)row * Hn + t;
    float v = a[off];
    if (b) v += b[off];
    if (c) v += c[off];
    float su = v, sq = v * v;
#pragma unroll
    for (int d = 16; d; d >>= 1) {
        su += __shfl_xor_sync(0xffffffffu, su, d);
        sq += __shfl_xor_sync(0xffffffffu, sq, d);
    }
    if ((t & 31) == 0) { s1[w] = su; s2[w] = sq; }
    __syncthreads();
    su = 0.0f; sq = 0.0f;
#pragma unroll
    for (int j = 0; j < 8; j++) { su += s1[j]; sq += s2[j]; }
    float mean = su * (1.0f / Hn);
    float var = sq * (1.0f / Hn) - mean * mean;
    float r = (v - mean) * rsqrtf(var + 1e-5f) * gam[t] + bet[t];
    out[off] = r;
    if (outb) outb[off] = __float2bfloat16(r);
}

// ---------------- host launch ----------------------------------------------
static void* sym_addr(const void* s) {
    void* p = nullptr;
    cudaGetSymbolAddress(&p, s);
    return p;
}

extern "C" void kernel_launch(void* const* d_in, const int* in_sizes, int n_in,
                              void* d_out, int out_size) {
    const float* x      = (const float*)d_in[0];
    const float* gcn_w  = (const float*)d_in[1];
    const float* gcn_b  = (const float*)d_in[2];
    const float* qkv_w  = (const float*)d_in[3];
    const float* qkv_b  = (const float*)d_in[4];
    const float* proj_w = (const float*)d_in[5];
    const float* proj_b = (const float*)d_in[6];
    const float* ln1_g  = (const float*)d_in[7];
    const float* ln1_b  = (const float*)d_in[8];
    const float* ln2_g  = (const float*)d_in[9];
    const float* ln2_b  = (const float*)d_in[10];
    const float* ffn1_w = (const float*)d_in[11];
    const float* ffn1_b = (const float*)d_in[12];
    const float* ffn2_w = (const float*)d_in[13];
    const float* ffn2_b = (const float*)d_in[14];
    const float* bias_e = (const float*)d_in[15];
    const float* oln1_g = (const float*)d_in[16];
    const float* oln1_b = (const float*)d_in[17];
    const float* oln2_g = (const float*)d_in[18];
    const float* oln2_b = (const float*)d_in[19];
    const float* offn1_w= (const float*)d_in[20];
    const float* offn1_b= (const float*)d_in[21];
    const float* offn2_w= (const float*)d_in[22];
    const float* offn2_b= (const float*)d_in[23];
    const int*   eidx   = (const int*)d_in[24];
    const int* src = eidx;
    const int* dst = eidx + En;
    float* out = (float*)d_out;

    float* p_xw  = (float*)sym_addr(g_xw);
    float* p_xl  = (float*)sym_addr(g_xlocal);
    float* p_buf = (float*)sym_addr(g_buf);
    float* p_h   = (float*)sym_addr(g_h);
    float* p_h2  = (float*)sym_addr(g_h2);
    float* p_y   = (float*)sym_addr(g_y);
    bf16* p_attb = (bf16*)sym_addr(g_attn_bf);
    bf16* p_hb   = (bf16*)sym_addr(g_h_bf);
    bf16* p_yb   = (bf16*)sym_addr(g_y_bf);
    bf16* p_ffb  = (bf16*)sym_addr(g_ff_bf);
    bf16* p_wproj= (bf16*)sym_addr(g_wproj);
    bf16* p_wf1  = (bf16*)sym_addr(g_wf1);
    bf16* p_wf2  = (bf16*)sym_addr(g_wf2);
    bf16* p_wo1  = (bf16*)sym_addr(g_wo1);
    bf16* p_wo2  = (bf16*)sym_addr(g_wo2);

    const int SM128 = 3 * (128 + 64) * 20 * 4;   // 46080
    const int SM64  = 3 * (64  + 64) * 20 * 4;   // 30720
    const int ATTN_SMEM = ATTN_SMEM_U32 * 4;     // 36896
    cudaFuncSetAttribute(gemm_bf16_kernel<128>, cudaFuncAttributeMaxDynamicSharedMemorySize, SM128);
    cudaFuncSetAttribute(gemm_bf16_kernel<64>,  cudaFuncAttributeMaxDynamicSharedMemorySize, SM64);
    cudaFuncSetAttribute(k_fill_xw,    cudaFuncAttributeMaxDynamicSharedMemorySize, SM64);
    cudaFuncSetAttribute(k_qkv_bfs,    cudaFuncAttributeMaxDynamicSharedMemorySize, SM128);
    cudaFuncSetAttribute(k_attn_gather, cudaFuncAttributeMaxDynamicSharedMemorySize, ATTN_SMEM);

    // graph prep + bf16 conversion
    init_cvt_kernel<<<3392, 256>>>(x, gcn_w, qkv_w, proj_w, ffn1_w, ffn2_w, offn1_w, offn2_w);
    edge_prep_kernel<<<En/256, 256>>>(src, dst);
    scan_kernel<<<1, 1024>>>();
    k_fill_xw<<<512 + En/256, 256, SM64>>>(src, dst, p_xw);

    // transformer (+ hidden bfs / gather)
    k_qkv_bfs<<<768 + Nn/8, 256, SM128>>>(qkv_b);
    k_attn_gather<<<512 + Nn, 256, ATTN_SMEM>>>(bias_e, gcn_b);
    gemm_bf16_kernel<64><<<dim3(4, 128), 256, SM64>>>(p_attb, p_wproj, proj_b, p_buf, Hn, Hn, 0, 0);
    ln_kernel<<<Nn, 256>>>(x, p_buf, nullptr, ln1_g, ln1_b, p_h, p_hb);
    gemm_bf16_kernel<128><<<dim3(16, 64), 256, SM128>>>(p_hb, p_wf1, ffn1_b, p_ffb, FFNn, Hn, 1, 1);
    gemm_bf16_kernel<64><<<dim3(4, 128), 256, SM64>>>(p_ffb, p_wf2, ffn2_b, p_buf, Hn, FFNn, 0, 0);
    ln_kernel<<<Nn, 256>>>(p_h, p_buf, nullptr, ln2_g, ln2_b, p_h2, nullptr);

    // GPS combine + outer FFN
    ln_kernel<<<Nn, 256>>>(x, p_xl, p_h2, oln1_g, oln1_b, p_y, p_yb);
    gemm_bf16_kernel<128><<<dim3(16, 64), 256, SM128>>>(p_yb, p_wo1, offn1_b, p_ffb, FFNn, Hn, 1, 1);
    gemm_bf16_kernel<64><<<dim3(4, 128), 256, SM64>>>(p_ffb, p_wo2, offn2_b, p_buf, Hn, FFNn, 0, 0);
    ln_kernel<<<Nn, 256>>>(p_y, p_buf, nullptr, oln2_g, oln2_b, out, nullptr);
}